// round 1
// baseline (speedup 1.0000x reference)
#include <cuda_runtime.h>
#include <math.h>

// ---------------------------------------------------------------------------
// CATB axial attention block, fp32 baseline.
// B=2, H=W=112, C=192, SPLIT=7, NHB=4, hd=24, hidden=768.
// Pipeline:
//   img = LN1(x)
//   qkv = img @ qkv_w^T                         (25088 x 576)
//   attention (2 axial branches, 32 windows x 4 heads each, N=784, hd=24)
//   xo  = x + att @ proj_w^T + proj_b
//   y   = LN2(xo)
//   out = xo + gelu(y @ fc1^T + b1) @ fc2^T + b2
// ---------------------------------------------------------------------------

#define BATCH 2
#define HH 112
#define WW 112
#define CC 192
#define LL (HH * WW)          // 12544
#define MROWS (BATCH * LL)    // 25088
#define CB 96
#define HD_ 24
#define NHB 4
#define NTOK 784              // 112*7
#define NPOS 2899             // (2*112-1)*(2*7-1)
#define HIDDEN 768

// -------------------------- scratch (device globals) -----------------------
__device__ float g_img[MROWS * CC];
__device__ float g_qkv[MROWS * 3 * CC];
__device__ float g_att[MROWS * CC];
__device__ float g_xo [MROWS * CC];
__device__ float g_y  [MROWS * CC];
__device__ float g_h  [MROWS * HIDDEN];
__device__ float g_pos[2 * NPOS * NHB];

// -------------------------- LayerNorm over C=192 ---------------------------
__global__ __launch_bounds__(256) void ln_kernel(
    const float* __restrict__ in, const float* __restrict__ w,
    const float* __restrict__ b, float* __restrict__ out)
{
    int row = blockIdx.x * 8 + (threadIdx.x >> 5);
    if (row >= MROWS) return;
    int lane = threadIdx.x & 31;
    const float* p = in + (long)row * CC;
    float v[6];
    float s = 0.f, s2 = 0.f;
#pragma unroll
    for (int u = 0; u < 6; u++) {
        v[u] = p[lane + u * 32];
        s += v[u];
        s2 += v[u] * v[u];
    }
#pragma unroll
    for (int off = 16; off > 0; off >>= 1) {
        s  += __shfl_xor_sync(0xffffffffu, s,  off);
        s2 += __shfl_xor_sync(0xffffffffu, s2, off);
    }
    float mu  = s * (1.f / CC);
    float var = s2 * (1.f / CC) - mu * mu;
    float inv = rsqrtf(var + 1e-5f);
    float* q = out + (long)row * CC;
#pragma unroll
    for (int u = 0; u < 6; u++) {
        int c = lane + u * 32;
        q[c] = (v[u] - mu) * inv * w[c] + b[c];
    }
}

// -------------------------- rel-pos-bias MLP -------------------------------
__device__ __forceinline__ void ln6_relu(float* v, const float* w, const float* b)
{
    float mu = 0.f;
#pragma unroll
    for (int i = 0; i < 6; i++) mu += v[i];
    mu *= (1.f / 6.f);
    float var = 0.f;
#pragma unroll
    for (int i = 0; i < 6; i++) { float d = v[i] - mu; var += d * d; }
    var *= (1.f / 6.f);
    float inv = rsqrtf(var + 1e-5f);
#pragma unroll
    for (int i = 0; i < 6; i++)
        v[i] = fmaxf((v[i] - mu) * inv * w[i] + b[i], 0.f);
}

__global__ void pos_mlp_kernel(
    const float* __restrict__ proj_w, const float* __restrict__ proj_b,
    const float* __restrict__ ln1_w,  const float* __restrict__ ln1_b,
    const float* __restrict__ fc1_w,  const float* __restrict__ fc1_b,
    const float* __restrict__ ln2_w,  const float* __restrict__ ln2_b,
    const float* __restrict__ fc2_w,  const float* __restrict__ fc2_b,
    const float* __restrict__ ln3_w,  const float* __restrict__ ln3_b,
    const float* __restrict__ fc3_w,  const float* __restrict__ fc3_b,
    float* __restrict__ out)
{
    int idx = blockIdx.x * blockDim.x + threadIdx.x;
    if (idx >= 2 * NPOS) return;
    int br = idx / NPOS, r = idx - br * NPOS;
    int Hsp = br ? 7 : 112;
    int Wsp = br ? 112 : 7;
    int W2 = 2 * Wsp - 1;
    int a = r / W2, bcol = r - a * W2;
    float ph = (float)(a - (Hsp - 1));
    float pw = (float)(bcol - (Wsp - 1));

    float t[6], u[6];
#pragma unroll
    for (int o = 0; o < 6; o++)
        t[o] = proj_w[(br * 6 + o) * 2 + 0] * ph +
               proj_w[(br * 6 + o) * 2 + 1] * pw + proj_b[br * 6 + o];
    ln6_relu(t, ln1_w + br * 6, ln1_b + br * 6);
#pragma unroll
    for (int o = 0; o < 6; o++) {
        float s = fc1_b[br * 6 + o];
#pragma unroll
        for (int i = 0; i < 6; i++) s += fc1_w[br * 36 + o * 6 + i] * t[i];
        u[o] = s;
    }
    ln6_relu(u, ln2_w + br * 6, ln2_b + br * 6);
#pragma unroll
    for (int o = 0; o < 6; o++) {
        float s = fc2_b[br * 6 + o];
#pragma unroll
        for (int i = 0; i < 6; i++) s += fc2_w[br * 36 + o * 6 + i] * u[i];
        t[o] = s;
    }
    ln6_relu(t, ln3_w + br * 6, ln3_b + br * 6);
#pragma unroll
    for (int h = 0; h < 4; h++) {
        float s = fc3_b[br * 4 + h];
#pragma unroll
        for (int i = 0; i < 6; i++) s += fc3_w[br * 24 + h * 6 + i] * t[i];
        out[(br * NPOS + r) * 4 + h] = s;
    }
}

// -------------------------- attention --------------------------------------
// 256 blocks: blockIdx.x = br*128 + win*4 + head, win = b*16 + w16.
// SMEM: K[784*24], V[784*24], scores[8 warps][2][784], pos column[2899].
#define ATTN_SMEM ((2 * NTOK * HD_ + 8 * 2 * NTOK + NPOS) * 4)

__global__ __launch_bounds__(256) void attn_kernel(
    const float* __restrict__ qkv, const float* __restrict__ pos,
    float* __restrict__ att_out)
{
    extern __shared__ float sm[];
    float* Ks = sm;                          // 784*24
    float* Vs = Ks + NTOK * HD_;             // 784*24
    float* Sc = Vs + NTOK * HD_;             // 8*2*784
    float* Ps = Sc + 8 * 2 * NTOK;           // 2899

    int bx   = blockIdx.x;
    int br   = bx >> 7;
    int rem  = bx & 127;
    int win  = rem >> 2;
    int head = rem & 3;
    int b    = win >> 4, w16 = win & 15;
    int tid  = threadIdx.x, lane = tid & 31, warp = tid >> 5;
    int cbase = br * CB + head * HD_;

    // load K, V for this (window, head) into smem
    for (int idx = tid; idx < NTOK * HD_; idx += 256) {
        int j = idx / HD_, d = idx - j * HD_;
        int h, w;
        if (br == 0) { int hj = j / 7;   h = hj;           w = w16 * 7 + (j - hj * 7); }
        else         { int hj = j / 112; h = w16 * 7 + hj; w = j - hj * 112; }
        long base = ((long)(b * LL + h * WW + w)) * 576 + cbase + d;
        Ks[j * HD_ + d] = qkv[base + 192];
        Vs[j * HD_ + d] = qkv[base + 384];
    }
    for (int r = tid; r < NPOS; r += 256)
        Ps[r] = pos[(br * NPOS + r) * 4 + head];
    __syncthreads();

    const float scale = 0.20412414523193154f; // 24^-0.5
    const int Hsp = br ? 7 : 112;
    const int Wsp = br ? 112 : 7;
    const int W2  = 2 * Wsp - 1;

    for (int i0 = warp * 2; i0 < NTOK; i0 += 16) {
        int i1 = i0 + 1;
        int hi0, wi0, l0, hi1, wi1, l1;
        if (br == 0) {
            hi0 = i0 / 7; wi0 = i0 - hi0 * 7; l0 = hi0 * WW + w16 * 7 + wi0;
            hi1 = i1 / 7; wi1 = i1 - hi1 * 7; l1 = hi1 * WW + w16 * 7 + wi1;
        } else {
            hi0 = i0 / 112; wi0 = i0 - hi0 * 112; l0 = (w16 * 7 + hi0) * WW + wi0;
            hi1 = i1 / 112; wi1 = i1 - hi1 * 112; l1 = (w16 * 7 + hi1) * WW + wi1;
        }
        // q rows (broadcast loads), pre-scaled
        float q0[24], q1[24];
        {
            const float* qp0 = qkv + ((long)(b * LL + l0)) * 576 + cbase;
            const float* qp1 = qkv + ((long)(b * LL + l1)) * 576 + cbase;
#pragma unroll
            for (int d = 0; d < 24; d++) { q0[d] = qp0[d] * scale; q1[d] = qp1[d] * scale; }
        }
        float* s0 = Sc + (warp * 2 + 0) * NTOK;
        float* s1 = Sc + (warp * 2 + 1) * NTOK;
        float m0 = -1e30f, m1 = -1e30f;
        int rb0 = (hi0 + Hsp - 1) * W2 + wi0 + Wsp - 1;
        int rb1 = (hi1 + Hsp - 1) * W2 + wi1 + Wsp - 1;

        for (int j = lane; j < NTOK; j += 32) {
            float a0 = 0.f, a1 = 0.f;
            const float* kp = Ks + j * HD_;
#pragma unroll
            for (int d4 = 0; d4 < 6; d4++) {
                float4 kv = *(const float4*)(kp + d4 * 4);
                a0 = fmaf(q0[d4*4+0], kv.x, a0); a1 = fmaf(q1[d4*4+0], kv.x, a1);
                a0 = fmaf(q0[d4*4+1], kv.y, a0); a1 = fmaf(q1[d4*4+1], kv.y, a1);
                a0 = fmaf(q0[d4*4+2], kv.z, a0); a1 = fmaf(q1[d4*4+2], kv.z, a1);
                a0 = fmaf(q0[d4*4+3], kv.w, a0); a1 = fmaf(q1[d4*4+3], kv.w, a1);
            }
            int hj, wj;
            if (br == 0) { hj = j / 7;   wj = j - hj * 7;   }
            else         { hj = j / 112; wj = j - hj * 112; }
            int roff = hj * W2 + wj;
            a0 += Ps[rb0 - roff];
            a1 += Ps[rb1 - roff];
            s0[j] = a0; s1[j] = a1;
            m0 = fmaxf(m0, a0); m1 = fmaxf(m1, a1);
        }
#pragma unroll
        for (int off = 16; off > 0; off >>= 1) {
            m0 = fmaxf(m0, __shfl_xor_sync(0xffffffffu, m0, off));
            m1 = fmaxf(m1, __shfl_xor_sync(0xffffffffu, m1, off));
        }
        float e0 = 0.f, e1 = 0.f;
        for (int j = lane; j < NTOK; j += 32) {
            float p = __expf(s0[j] - m0); s0[j] = p; e0 += p;
            p = __expf(s1[j] - m1);       s1[j] = p; e1 += p;
        }
#pragma unroll
        for (int off = 16; off > 0; off >>= 1) {
            e0 += __shfl_xor_sync(0xffffffffu, e0, off);
            e1 += __shfl_xor_sync(0xffffffffu, e1, off);
        }
        float inv0 = 1.f / e0, inv1 = 1.f / e1;

        float acc0[24], acc1[24];
#pragma unroll
        for (int d = 0; d < 24; d++) { acc0[d] = 0.f; acc1[d] = 0.f; }
        for (int j = lane; j < NTOK; j += 32) {
            float p0 = s0[j], p1 = s1[j];
            const float* vp = Vs + j * HD_;
#pragma unroll
            for (int d4 = 0; d4 < 6; d4++) {
                float4 vv = *(const float4*)(vp + d4 * 4);
                acc0[d4*4+0] = fmaf(p0, vv.x, acc0[d4*4+0]);
                acc0[d4*4+1] = fmaf(p0, vv.y, acc0[d4*4+1]);
                acc0[d4*4+2] = fmaf(p0, vv.z, acc0[d4*4+2]);
                acc0[d4*4+3] = fmaf(p0, vv.w, acc0[d4*4+3]);
                acc1[d4*4+0] = fmaf(p1, vv.x, acc1[d4*4+0]);
                acc1[d4*4+1] = fmaf(p1, vv.y, acc1[d4*4+1]);
                acc1[d4*4+2] = fmaf(p1, vv.z, acc1[d4*4+2]);
                acc1[d4*4+3] = fmaf(p1, vv.w, acc1[d4*4+3]);
            }
        }
#pragma unroll
        for (int d = 0; d < 24; d++) {
#pragma unroll
            for (int off = 16; off > 0; off >>= 1) {
                acc0[d] += __shfl_xor_sync(0xffffffffu, acc0[d], off);
                acc1[d] += __shfl_xor_sync(0xffffffffu, acc1[d], off);
            }
        }
        if (lane == 0) {
            float* o0 = att_out + ((long)(b * LL + l0)) * CC + cbase;
            float* o1 = att_out + ((long)(b * LL + l1)) * CC + cbase;
#pragma unroll
            for (int d4 = 0; d4 < 6; d4++) {
                *(float4*)(o0 + d4 * 4) = make_float4(
                    acc0[d4*4+0]*inv0, acc0[d4*4+1]*inv0, acc0[d4*4+2]*inv0, acc0[d4*4+3]*inv0);
                *(float4*)(o1 + d4 * 4) = make_float4(
                    acc1[d4*4+0]*inv1, acc1[d4*4+1]*inv1, acc1[d4*4+2]*inv1, acc1[d4*4+3]*inv1);
            }
        }
    }
}

// -------------------------- SGEMM (NT): out[M,N] = A[M,K] @ W[N,K]^T -------
// BM=128, BN=64, BK=16, 256 threads, 8x4 microtile.
// MODE 0: plain. 1: +bias +res. 2: +bias, gelu. 3: +bias +res.
__device__ __forceinline__ float gelu_f(float x)
{
    return 0.5f * x * (1.f + erff(x * 0.7071067811865476f));
}

template <int MODE>
__global__ __launch_bounds__(256) void gemm_kernel(
    const float* __restrict__ A, const float* __restrict__ Wt,
    const float* __restrict__ bias, const float* __restrict__ res,
    float* __restrict__ out, int N, int K)
{
    __shared__ float As[16][128];
    __shared__ float Bs[16][64];
    const int m0 = blockIdx.x * 128;
    const int n0 = blockIdx.y * 64;
    const int tid = threadIdx.x;
    const int tx = tid & 15, ty = tid >> 4;

    float c[8][4];
#pragma unroll
    for (int u = 0; u < 8; u++)
#pragma unroll
        for (int v = 0; v < 4; v++) c[u][v] = 0.f;

    for (int kt = 0; kt < K; kt += 16) {
#pragma unroll
        for (int i = 0; i < 2; i++) {
            int f = tid + i * 256;
            int m = f >> 2, k4 = (f & 3) * 4;
            float4 a = *(const float4*)&A[(long)(m0 + m) * K + kt + k4];
            As[k4 + 0][m] = a.x; As[k4 + 1][m] = a.y;
            As[k4 + 2][m] = a.z; As[k4 + 3][m] = a.w;
        }
        {
            int n = tid >> 2, k4 = (tid & 3) * 4;
            float4 bv = *(const float4*)&Wt[(long)(n0 + n) * K + kt + k4];
            Bs[k4 + 0][n] = bv.x; Bs[k4 + 1][n] = bv.y;
            Bs[k4 + 2][n] = bv.z; Bs[k4 + 3][n] = bv.w;
        }
        __syncthreads();
#pragma unroll
        for (int kk = 0; kk < 16; kk++) {
            float4 a0 = *(const float4*)&As[kk][ty * 8];
            float4 a1 = *(const float4*)&As[kk][ty * 8 + 4];
            float4 bv = *(const float4*)&Bs[kk][tx * 4];
            float ar[8] = {a0.x, a0.y, a0.z, a0.w, a1.x, a1.y, a1.z, a1.w};
            float brr[4] = {bv.x, bv.y, bv.z, bv.w};
#pragma unroll
            for (int u = 0; u < 8; u++)
#pragma unroll
                for (int v = 0; v < 4; v++) c[u][v] = fmaf(ar[u], brr[v], c[u][v]);
        }
        __syncthreads();
    }

    float4 bb = make_float4(0.f, 0.f, 0.f, 0.f);
    if (MODE >= 1) bb = *(const float4*)&bias[n0 + tx * 4];
#pragma unroll
    for (int u = 0; u < 8; u++) {
        long rowoff = (long)(m0 + ty * 8 + u) * N + n0 + tx * 4;
        float4 o = make_float4(c[u][0], c[u][1], c[u][2], c[u][3]);
        if (MODE >= 1) { o.x += bb.x; o.y += bb.y; o.z += bb.z; o.w += bb.w; }
        if (MODE == 1 || MODE == 3) {
            float4 rr = *(const float4*)&res[rowoff];
            o.x += rr.x; o.y += rr.y; o.z += rr.z; o.w += rr.w;
        }
        if (MODE == 2) {
            o.x = gelu_f(o.x); o.y = gelu_f(o.y);
            o.z = gelu_f(o.z); o.w = gelu_f(o.w);
        }
        *(float4*)&out[rowoff] = o;
    }
}

// -------------------------- launch -----------------------------------------
extern "C" void kernel_launch(void* const* d_in, const int* in_sizes, int n_in,
                              void* d_out, int out_size)
{
    const float* x      = (const float*)d_in[0];
    const float* n1w    = (const float*)d_in[1];
    const float* n1b    = (const float*)d_in[2];
    const float* qkv_w  = (const float*)d_in[3];
    const float* proj_w = (const float*)d_in[4];
    const float* proj_b = (const float*)d_in[5];
    const float* n2w    = (const float*)d_in[6];
    const float* n2b    = (const float*)d_in[7];
    const float* fc1_w  = (const float*)d_in[8];
    const float* fc1_b  = (const float*)d_in[9];
    const float* fc2_w  = (const float*)d_in[10];
    const float* fc2_b  = (const float*)d_in[11];
    const float* pproj_w = (const float*)d_in[12];
    const float* pproj_b = (const float*)d_in[13];
    const float* pln1_w = (const float*)d_in[14];
    const float* pln1_b = (const float*)d_in[15];
    const float* pfc1_w = (const float*)d_in[16];
    const float* pfc1_b = (const float*)d_in[17];
    const float* pln2_w = (const float*)d_in[18];
    const float* pln2_b = (const float*)d_in[19];
    const float* pfc2_w = (const float*)d_in[20];
    const float* pfc2_b = (const float*)d_in[21];
    const float* pln3_w = (const float*)d_in[22];
    const float* pln3_b = (const float*)d_in[23];
    const float* pfc3_w = (const float*)d_in[24];
    const float* pfc3_b = (const float*)d_in[25];
    float* out = (float*)d_out;

    float *img, *qkvb, *att, *xo, *y, *hbuf, *pos;
    cudaGetSymbolAddress((void**)&img,  g_img);
    cudaGetSymbolAddress((void**)&qkvb, g_qkv);
    cudaGetSymbolAddress((void**)&att,  g_att);
    cudaGetSymbolAddress((void**)&xo,   g_xo);
    cudaGetSymbolAddress((void**)&y,    g_y);
    cudaGetSymbolAddress((void**)&hbuf, g_h);
    cudaGetSymbolAddress((void**)&pos,  g_pos);

    cudaFuncSetAttribute(attn_kernel,
                         cudaFuncAttributeMaxDynamicSharedMemorySize, ATTN_SMEM);

    // 1. relative-position-bias tables (2 x 2899 x 4)
    pos_mlp_kernel<<<(2 * NPOS + 127) / 128, 128>>>(
        pproj_w, pproj_b, pln1_w, pln1_b, pfc1_w, pfc1_b,
        pln2_w, pln2_b, pfc2_w, pfc2_b, pln3_w, pln3_b, pfc3_w, pfc3_b, pos);
    // 2. LN1
    ln_kernel<<<MROWS / 8, 256>>>(x, n1w, n1b, img);
    // 3. qkv projection: (25088,192) @ (576,192)^T
    gemm_kernel<0><<<dim3(MROWS / 128, 576 / 64), 256>>>(
        img, qkv_w, nullptr, nullptr, qkvb, 576, 192);
    // 4. axial window attention, both branches
    attn_kernel<<<256, 256, ATTN_SMEM>>>(qkvb, pos, att);
    // 5. proj + residual -> xo
    gemm_kernel<1><<<dim3(MROWS / 128, 192 / 64), 256>>>(
        att, proj_w, proj_b, x, xo, 192, 192);
    // 6. LN2
    ln_kernel<<<MROWS / 8, 256>>>(xo, n2w, n2b, y);
    // 7. fc1 + gelu
    gemm_kernel<2><<<dim3(MROWS / 128, HIDDEN / 64), 256>>>(
        y, fc1_w, fc1_b, nullptr, hbuf, HIDDEN, 192);
    // 8. fc2 + bias + residual -> out
    gemm_kernel<3><<<dim3(MROWS / 128, 192 / 64), 256>>>(
        hbuf, fc2_w, fc2_b, xo, out, 192, HIDDEN);
}